// round 2
// baseline (speedup 1.0000x reference)
#include <cuda_runtime.h>
#include <math.h>

// Problem constants (fixed by the dataset: B=8, D=256, C=2)
#define D_DIM 256
#define B_DIM 8

__global__ __launch_bounds__(256) void slice_phase_kernel(
    const float* __restrict__ vol,     // (B, 2, D, D, D)
    const float* __restrict__ rot,     // (B, 3, 3)
    const float* __restrict__ trans,   // (B, 2)
    float* __restrict__ out)           // (B, 2, D, D)
{
    const int j = threadIdx.x;   // fast output axis
    const int i = blockIdx.x;    // second output axis
    const int b = blockIdx.y;

    // Rotation row-major: R[r*3+c]. Thread-uniform loads.
    const float* R = rot + b * 9;
    const float r00 = __ldg(R + 0), r01 = __ldg(R + 1);
    const float r10 = __ldg(R + 3), r11 = __ldg(R + 4);
    const float r20 = __ldg(R + 6), r21 = __ldg(R + 7);

    // Pixel (h=j, w=i) of the pre-transpose projection:
    // gx = coords1d[i], gy = coords1d[j]
    const float gx = (float)i - 128.0f;
    const float gy = (float)j - 128.0f;

    // coords (x,y,z) = R * [gx, gy, 0] + D/2
    float x = fmaf(r00, gx, fmaf(r01, gy, 128.0f));
    float y = fmaf(r10, gx, fmaf(r11, gy, 128.0f));
    float z = fmaf(r20, gx, fmaf(r21, gy, 128.0f));

    // clamp to [0, D-1]
    const float lim = 255.0f;
    x = fminf(fmaxf(x, 0.0f), lim);
    y = fminf(fmaxf(y, 0.0f), lim);
    z = fminf(fmaxf(z, 0.0f), lim);

    const float xf = floorf(x), yf = floorf(y), zf = floorf(z);
    const float fx = x - xf, fy = y - yf, fz = z - zf;
    const int x0 = (int)xf, y0 = (int)yf, z0 = (int)zf;
    const int x1 = min(x0 + 1, 255);
    const int y1 = min(y0 + 1, 255);
    const int z1 = min(z0 + 1, 255);

    // Flat voxel indices (D=256 -> shifts)
    const long long batch_off = (long long)b * 2LL * D_DIM * D_DIM * D_DIM;
    const float* v0 = vol + batch_off;                           // channel 0 (re)
    const float* v1 = v0 + (long long)D_DIM * D_DIM * D_DIM;     // channel 1 (im)

    const int i000 = ((z0 << 8) + y0 << 8) + x0;
    const int i001 = ((z0 << 8) + y0 << 8) + x1;
    const int i010 = ((z0 << 8) + y1 << 8) + x0;
    const int i011 = ((z0 << 8) + y1 << 8) + x1;
    const int i100 = ((z1 << 8) + y0 << 8) + x0;
    const int i101 = ((z1 << 8) + y0 << 8) + x1;
    const int i110 = ((z1 << 8) + y1 << 8) + x0;
    const int i111 = ((z1 << 8) + y1 << 8) + x1;

    // Issue all 16 gathers up-front for max MLP
    const float a000 = __ldg(v0 + i000), a001 = __ldg(v0 + i001);
    const float a010 = __ldg(v0 + i010), a011 = __ldg(v0 + i011);
    const float a100 = __ldg(v0 + i100), a101 = __ldg(v0 + i101);
    const float a110 = __ldg(v0 + i110), a111 = __ldg(v0 + i111);
    const float b000 = __ldg(v1 + i000), b001 = __ldg(v1 + i001);
    const float b010 = __ldg(v1 + i010), b011 = __ldg(v1 + i011);
    const float b100 = __ldg(v1 + i100), b101 = __ldg(v1 + i101);
    const float b110 = __ldg(v1 + i110), b111 = __ldg(v1 + i111);

    const float w000 = (1.0f - fz) * (1.0f - fy) * (1.0f - fx);
    const float w001 = (1.0f - fz) * (1.0f - fy) * fx;
    const float w010 = (1.0f - fz) * fy * (1.0f - fx);
    const float w011 = (1.0f - fz) * fy * fx;
    const float w100 = fz * (1.0f - fy) * (1.0f - fx);
    const float w101 = fz * (1.0f - fy) * fx;
    const float w110 = fz * fy * (1.0f - fx);
    const float w111 = fz * fy * fx;

    float re = a000 * w000 + a001 * w001 + a010 * w010 + a011 * w011
             + a100 * w100 + a101 * w101 + a110 * w110 + a111 * w111;
    float im = b000 * w000 + b001 * w001 + b010 * w010 + b011 * w011
             + b100 * w100 + b101 * w101 + b110 * w110 + b111 * w111;

    // * sqrt(D) = 16
    re *= 16.0f;
    im *= 16.0f;

    // Phase shift:
    // t0 = -trans[b][1]*128, t1 = -trans[b][0]*128
    // ang = -(2*pi/256) * (t0*(i-128) + t1*(j-128))
    const float t0 = -__ldg(trans + b * 2 + 1) * 128.0f;
    const float t1 = -__ldg(trans + b * 2 + 0) * 128.0f;
    const float ki = (float)i - 128.0f;
    const float kj = (float)j - 128.0f;
    const float TWO_PI_OVER_D = 6.2831853071795864769f / 256.0f;
    const float ang = -TWO_PI_OVER_D * (t0 * ki + t1 * kj);
    float sn, cs;
    sincosf(ang, &sn, &cs);

    // out[b, 0, i, j], out[b, 1, i, j]
    const long long out_base = ((long long)b * 2 * D_DIM + i) * D_DIM + j;
    out[out_base] = re * cs - im * sn;
    out[out_base + (long long)D_DIM * D_DIM] = re * sn + im * cs;
}

extern "C" void kernel_launch(void* const* d_in, const int* in_sizes, int n_in,
                              void* d_out, int out_size) {
    const float* vol   = (const float*)d_in[0];   // protein_samples (8,2,256,256,256)
    const float* rot   = (const float*)d_in[1];   // rotation_samples (8,3,3)
    const float* trans = (const float*)d_in[2];   // translation_samples (8,2)
    float* out = (float*)d_out;                    // (8,2,256,256)

    dim3 grid(D_DIM, B_DIM);
    dim3 block(D_DIM);
    slice_phase_kernel<<<grid, block>>>(vol, rot, trans, out);
}

// round 7
// speedup vs baseline: 1.1601x; 1.1601x over previous
#include <cuda_runtime.h>
#include <math.h>

// Problem constants (fixed by the dataset: B=8, D=256, C=2)
#define D_DIM 256
#define B_DIM 8

// Block = 256 threads covering a 16x16 (i x j) output tile.
// Lane decomposition: each WARP covers an 8(j) x 4(i) patch -> compact 3D
// gather footprint (vs. a 32-long line), boosting L1/L2 sector sharing.
__global__ __launch_bounds__(256) void slice_phase_kernel(
    const float* __restrict__ vol,     // (B, 2, D, D, D)
    const float* __restrict__ rot,     // (B, 3, 3)
    const float* __restrict__ trans,   // (B, 2)
    float* __restrict__ out)           // (B, 2, D, D)
{
    const int t = threadIdx.x;
    // bits: b0-2 -> dj(0..7), b3-4 -> di(0..3), b5 -> +8 j, b6-7 -> +4,+8 i
    const int dj = (t & 7) | ((t >> 2) & 8);          // (t&7) + ((t>>5)&1)*8
    const int di = ((t >> 3) & 3) | ((t >> 4) & 12);  // ((t>>3)&3) + (t>>6)*4

    const int j = (blockIdx.x << 4) + dj;
    const int i = (blockIdx.y << 4) + di;
    const int b = blockIdx.z;

    // Rotation row-major: R[r*3+c]. Thread-uniform loads.
    const float* R = rot + b * 9;
    const float r00 = __ldg(R + 0), r01 = __ldg(R + 1);
    const float r10 = __ldg(R + 3), r11 = __ldg(R + 4);
    const float r20 = __ldg(R + 6), r21 = __ldg(R + 7);

    // gx = coords1d[i], gy = coords1d[j]
    const float gx = (float)i - 128.0f;
    const float gy = (float)j - 128.0f;

    // coords (x,y,z) = R * [gx, gy, 0] + D/2
    float x = fmaf(r00, gx, fmaf(r01, gy, 128.0f));
    float y = fmaf(r10, gx, fmaf(r11, gy, 128.0f));
    float z = fmaf(r20, gx, fmaf(r21, gy, 128.0f));

    // clamp to [0, D-1]
    const float lim = 255.0f;
    x = fminf(fmaxf(x, 0.0f), lim);
    y = fminf(fmaxf(y, 0.0f), lim);
    z = fminf(fmaxf(z, 0.0f), lim);

    const float xf = floorf(x), yf = floorf(y), zf = floorf(z);
    const float fx = x - xf, fy = y - yf, fz = z - zf;
    const int x0 = (int)xf, y0 = (int)yf, z0 = (int)zf;
    const int x1 = min(x0 + 1, 255);
    const int y1 = min(y0 + 1, 255);
    const int z1 = min(z0 + 1, 255);

    // Flat voxel indices (D=256 -> shifts)
    const long long batch_off = (long long)b * 2LL * D_DIM * D_DIM * D_DIM;
    const float* v0 = vol + batch_off;                           // channel 0 (re)
    const float* v1 = v0 + (long long)D_DIM * D_DIM * D_DIM;     // channel 1 (im)

    const int zy00 = ((z0 << 8) + y0) << 8;
    const int zy01 = ((z0 << 8) + y1) << 8;
    const int zy10 = ((z1 << 8) + y0) << 8;
    const int zy11 = ((z1 << 8) + y1) << 8;

    const int i000 = zy00 + x0, i001 = zy00 + x1;
    const int i010 = zy01 + x0, i011 = zy01 + x1;
    const int i100 = zy10 + x0, i101 = zy10 + x1;
    const int i110 = zy11 + x0, i111 = zy11 + x1;

    // Issue all 16 gathers up-front for max MLP
    const float a000 = __ldg(v0 + i000), a001 = __ldg(v0 + i001);
    const float a010 = __ldg(v0 + i010), a011 = __ldg(v0 + i011);
    const float a100 = __ldg(v0 + i100), a101 = __ldg(v0 + i101);
    const float a110 = __ldg(v0 + i110), a111 = __ldg(v0 + i111);
    const float b000 = __ldg(v1 + i000), b001 = __ldg(v1 + i001);
    const float b010 = __ldg(v1 + i010), b011 = __ldg(v1 + i011);
    const float b100 = __ldg(v1 + i100), b101 = __ldg(v1 + i101);
    const float b110 = __ldg(v1 + i110), b111 = __ldg(v1 + i111);

    const float gz = 1.0f - fz, gy_ = 1.0f - fy, gx_ = 1.0f - fx;
    const float wz0y0 = gz * gy_, wz0y1 = gz * fy;
    const float wz1y0 = fz * gy_, wz1y1 = fz * fy;

    const float w000 = wz0y0 * gx_, w001 = wz0y0 * fx;
    const float w010 = wz0y1 * gx_, w011 = wz0y1 * fx;
    const float w100 = wz1y0 * gx_, w101 = wz1y0 * fx;
    const float w110 = wz1y1 * gx_, w111 = wz1y1 * fx;

    float re = a000 * w000 + a001 * w001 + a010 * w010 + a011 * w011
             + a100 * w100 + a101 * w101 + a110 * w110 + a111 * w111;
    float im = b000 * w000 + b001 * w001 + b010 * w010 + b011 * w011
             + b100 * w100 + b101 * w101 + b110 * w110 + b111 * w111;

    // * sqrt(D) = 16
    re *= 16.0f;
    im *= 16.0f;

    // Phase shift:
    // t0 = -trans[b][1]*128, t1 = -trans[b][0]*128
    // ang = -(2*pi/256) * (t0*(i-128) + t1*(j-128))
    const float t0 = -__ldg(trans + b * 2 + 1) * 128.0f;
    const float t1 = -__ldg(trans + b * 2 + 0) * 128.0f;
    const float ki = (float)i - 128.0f;
    const float kj = (float)j - 128.0f;
    const float TWO_PI_OVER_D = 6.2831853071795864769f / 256.0f;

    // Exact period-256 reduction of s keeps |ang| <= pi so the fast
    // hardware sin/cos path is accurate (no Payne-Hanek slow path).
    // s_red = s - 256*rint(s/256) is exact in fp32 here (|s| <= 32768).
    float s = fmaf(t0, ki, t1 * kj);
    s = fmaf(-256.0f, rintf(s * (1.0f / 256.0f)), s);
    const float ang = -TWO_PI_OVER_D * s;
    float sn, cs;
    __sincosf(ang, &sn, &cs);

    // out[b, 0, i, j], out[b, 1, i, j]
    const long long out_base = ((long long)b * 2 * D_DIM + i) * D_DIM + j;
    out[out_base] = re * cs - im * sn;
    out[out_base + (long long)D_DIM * D_DIM] = re * sn + im * cs;
}

extern "C" void kernel_launch(void* const* d_in, const int* in_sizes, int n_in,
                              void* d_out, int out_size) {
    const float* vol   = (const float*)d_in[0];   // protein_samples (8,2,256,256,256)
    const float* rot   = (const float*)d_in[1];   // rotation_samples (8,3,3)
    const float* trans = (const float*)d_in[2];   // translation_samples (8,2)
    float* out = (float*)d_out;                    // (8,2,256,256)

    dim3 grid(D_DIM / 16, D_DIM / 16, B_DIM);
    dim3 block(256);
    slice_phase_kernel<<<grid, block>>>(vol, rot, trans, out);
}